// round 4
// baseline (speedup 1.0000x reference)
#include <cuda_runtime.h>
#include <cstdint>

// Problem constants (shapes fixed by the dataset; strides taken from in_sizes at runtime)
#define D 64
#define M_MAX 1000000

// Scratch: y_all^T, m-major: g_yT[m*64 + d] = (W @ values)[d, m].
// __device__ global = the sanctioned allocation-free scratch (256 MB).
__device__ float g_yT[(size_t)M_MAX * D];

// ---------- f32x2 helpers (sm_103a packed fp32: 2x FFMA throughput vs 3-reg FFMA) ----------
__device__ __forceinline__ unsigned long long splat2(float v) {
    unsigned long long r;
    unsigned int vi = __float_as_uint(v);
    asm("mov.b64 %0, {%1, %1};" : "=l"(r) : "r"(vi));
    return r;
}
__device__ __forceinline__ void fma2(unsigned long long& acc, unsigned long long a, unsigned long long b) {
    asm("fma.rn.f32x2 %0, %1, %2, %0;" : "+l"(acc) : "l"(a), "l"(b));
}
__device__ __forceinline__ float2 unpack2(unsigned long long v) {
    unsigned int lo, hi;
    asm("mov.b64 {%0, %1}, %2;" : "=r"(lo), "=r"(hi) : "l"(v));
    return make_float2(__uint_as_float(lo), __uint_as_float(hi));
}

// ---------- K1: y_all^T[m, :] = W @ values[:, m] for ALL m ----------
// Thread handles 2 m-columns, all 64 d as 32 f32x2 (d-pair) accumulators.
// Per k: 2 LDG (coalesced along m), 2 splats, 32 LDS.64 (broadcast weight pairs), 64 FFMA2.
// LDS:FFMA2 = 1:2 -> FFMA2-bound at rt 2 = full 128 FMA/cyc/SM fp32 rate.
__global__ __launch_bounds__(128)
void k1_gemm(const float* __restrict__ values, const float* __restrict__ weight, int M) {
    __shared__ float ws[D * D];  // ws[k*64 + d] (transposed: k-major)
    int tid = threadIdx.x;
    for (int i = tid; i < D * D; i += 128) {
        int d = i >> 6, k = i & 63;       // weight[d][k] row-major
        ws[k * D + d] = weight[i];
    }
    __syncthreads();

    long long m0 = (long long)blockIdx.x * 256 + tid;
    long long m1 = m0 + 128;
    bool p0 = m0 < M, p1 = m1 < M;

    unsigned long long acc0[32], acc1[32];
#pragma unroll
    for (int i = 0; i < 32; i++) { acc0[i] = 0ull; acc1[i] = 0ull; }

    const unsigned long long* wp = (const unsigned long long*)ws;  // wp[k*32 + dp] = {w[k][2dp], w[k][2dp+1]}

#pragma unroll 4
    for (int k = 0; k < D; k++) {
        float v0 = p0 ? values[(size_t)k * M + m0] : 0.0f;
        float v1 = p1 ? values[(size_t)k * M + m1] : 0.0f;
        unsigned long long v0p = splat2(v0);
        unsigned long long v1p = splat2(v1);
#pragma unroll
        for (int dp = 0; dp < 32; dp++) {
            unsigned long long w2 = wp[k * 32 + dp];  // LDS.64, uniform -> broadcast
            fma2(acc0[dp], w2, v0p);
            fma2(acc1[dp], w2, v1p);
        }
    }

    if (p0) {
        float4* o = (float4*)&g_yT[(size_t)m0 * D];
#pragma unroll
        for (int dp = 0; dp < 32; dp += 2) {
            float2 a = unpack2(acc0[dp]);
            float2 b = unpack2(acc0[dp + 1]);
            o[dp >> 1] = make_float4(a.x, a.y, b.x, b.y);
        }
    }
    if (p1) {
        float4* o = (float4*)&g_yT[(size_t)m1 * D];
#pragma unroll
        for (int dp = 0; dp < 32; dp += 2) {
            float2 a = unpack2(acc1[dp]);
            float2 b = unpack2(acc1[dp + 1]);
            o[dp >> 1] = make_float4(a.x, a.y, b.x, b.y);
        }
    }
}

// ---------- K2: out[:, j] = y_all^T[in_idx[out_idx[j]], :], transposed via smem ----------
// Block handles 64 output columns. Gather reads are contiguous 256B per column
// (warp reads 8 cols x 64B chunks); writes are 128B-coalesced along j per d-row.
#define JT 64
__global__ __launch_bounds__(256)
void k2_gather(const int* __restrict__ in_idx, const int* __restrict__ out_idx,
               float* __restrict__ out, int n_out) {
    __shared__ float ys[JT][D + 1];   // +1 pad: conflict-free transposed reads
    __shared__ int cols[JT];

    int t = threadIdx.x;
    int j0 = blockIdx.x * JT;

    if (t < JT) {
        int jj = j0 + t;
        int c = 0;
        if (jj < n_out) {
            int oj = out_idx[jj];
            c = in_idx[oj];
        }
        cols[t] = c;
    }
    __syncthreads();

    // Gather: 4 threads per column, each loads 4x float4 (64B chunks contiguous per group)
    int col = t >> 2;   // 0..63
    int sub = t & 3;    // 0..3
    long long c = cols[col];
    const float4* src = (const float4*)&g_yT[(size_t)c * D];
#pragma unroll
    for (int i = 0; i < 4; i++) {
        int q = i * 4 + sub;          // float4 index 0..15
        float4 v = src[q];
        float* dst = &ys[col][q * 4];
        dst[0] = v.x; dst[1] = v.y; dst[2] = v.z; dst[3] = v.w;
    }
    __syncthreads();

    // Transposed write-out: warp writes 128B contiguous along j for a fixed d
#pragma unroll
    for (int r = 0; r < 16; r++) {
        int flat = r * 256 + t;
        int d = flat >> 6;
        int jl = flat & 63;
        int jj = j0 + jl;
        if (jj < n_out)
            out[(size_t)d * n_out + jj] = ys[jl][d];
    }
}

extern "C" void kernel_launch(void* const* d_in, const int* in_sizes, int n_in,
                              void* d_out, int out_size) {
    const float* values  = (const float*)d_in[0];   // (64, M) row-major
    const float* weight  = (const float*)d_in[1];   // (64, 64) row-major
    const int*   in_idx  = (const int*)d_in[2];     // (N_IN,)
    const int*   out_idx = (const int*)d_in[3];     // (N_OUT,)
    float*       out     = (float*)d_out;           // (64, N_OUT) row-major

    int M     = in_sizes[0] / D;
    int n_out = in_sizes[3];

    int g1 = (M + 255) / 256;
    k1_gemm<<<g1, 128>>>(values, weight, M);

    int g2 = (n_out + JT - 1) / JT;
    k2_gather<<<g2, 256>>>(in_idx, out_idx, out, n_out);
}

// round 5
// speedup vs baseline: 1.3404x; 1.3404x over previous
#include <cuda_runtime.h>
#include <cstdint>

#define D 64
#define M_MAX 1000000

// Scratch: y_all^T, m-major: g_yT[m*64 + d] = (W @ values)[d, m]. (256 MB)
__device__ float g_yT[(size_t)M_MAX * D];

// ---------- f32x2 helpers (sm_103a packed fp32: 2x FFMA throughput) ----------
__device__ __forceinline__ unsigned long long splat2(float v) {
    unsigned long long r;
    unsigned int vi = __float_as_uint(v);
    asm("mov.b64 %0, {%1, %1};" : "=l"(r) : "r"(vi));
    return r;
}
__device__ __forceinline__ void fma2(unsigned long long& acc, unsigned long long a, unsigned long long b) {
    asm("fma.rn.f32x2 %0, %1, %2, %0;" : "+l"(acc) : "l"(a), "l"(b));
}
__device__ __forceinline__ float2 unpack2(unsigned long long v) {
    unsigned int lo, hi;
    asm("mov.b64 {%0, %1}, %2;" : "=r"(lo), "=r"(hi) : "l"(v));
    return make_float2(__uint_as_float(lo), __uint_as_float(hi));
}

// ---------- K1: y_all^T[m, :] = W @ values[:, m] for ALL m ----------
// Thread handles 2 ADJACENT m-columns via one float2 LDG per k (coalesced).
// 8-deep double-buffered prefetch hides the ~577cyc DRAM latency behind
// ~768 warp-cycles of FFMA2 work per chunk. Issue floor ~96 instr/k/warp.
__global__ __launch_bounds__(128)
void k1_gemm(const float* __restrict__ values, const float* __restrict__ weight, int M) {
    __shared__ float ws[D * D];  // ws[k*64 + d] (k-major)
    int tid = threadIdx.x;
    for (int i = tid; i < D * D; i += 128) {
        int d = i >> 6, k = i & 63;       // weight[d][k] row-major
        ws[k * D + d] = weight[i];
    }
    __syncthreads();

    long long m0 = ((long long)blockIdx.x * 128 + tid) * 2;   // adjacent pair (m0, m0+1)
    bool ok = (m0 + 1) < (long long)M;                         // M even -> pair fully in or out
    // Safe pointer for out-of-range threads (they still "compute", never store)
    const float2* p = (const float2*)(values + (ok ? m0 : 0));
    size_t strideK = (size_t)M / 2;   // float2 elements per k-row (M even)

    unsigned long long acc0[32], acc1[32];
#pragma unroll
    for (int i = 0; i < 32; i++) { acc0[i] = 0ull; acc1[i] = 0ull; }

    const unsigned long long* wp = (const unsigned long long*)ws;  // wp[k*32+dp] = {w[k][2dp], w[k][2dp+1]}

    float2 cur[8], nxt[8];
#pragma unroll
    for (int kk = 0; kk < 8; kk++)
        cur[kk] = __ldg(p + (size_t)kk * strideK);

    for (int k0 = 0; k0 < 64; k0 += 8) {
        if (k0 + 8 < 64) {
#pragma unroll
            for (int kk = 0; kk < 8; kk++)
                nxt[kk] = __ldg(p + (size_t)(k0 + 8 + kk) * strideK);
        }
#pragma unroll
        for (int kk = 0; kk < 8; kk++) {
            unsigned long long v0p = splat2(cur[kk].x);
            unsigned long long v1p = splat2(cur[kk].y);
            const unsigned long long* wrow = wp + (size_t)(k0 + kk) * 32;
#pragma unroll
            for (int dp = 0; dp < 32; dp++) {
                unsigned long long w2 = wrow[dp];  // LDS.64, broadcast
                fma2(acc0[dp], w2, v0p);
                fma2(acc1[dp], w2, v1p);
            }
        }
#pragma unroll
        for (int kk = 0; kk < 8; kk++) cur[kk] = nxt[kk];
    }

    if (ok) {
        float4* o0 = (float4*)&g_yT[(size_t)m0 * D];
        float4* o1 = (float4*)&g_yT[(size_t)(m0 + 1) * D];
#pragma unroll
        for (int dp = 0; dp < 32; dp += 2) {
            float2 a0 = unpack2(acc0[dp]);
            float2 b0 = unpack2(acc0[dp + 1]);
            o0[dp >> 1] = make_float4(a0.x, a0.y, b0.x, b0.y);
            float2 a1 = unpack2(acc1[dp]);
            float2 b1 = unpack2(acc1[dp + 1]);
            o1[dp >> 1] = make_float4(a1.x, a1.y, b1.x, b1.y);
        }
    }
}

// ---------- K2: out[:, j] = y_all^T[in_idx[out_idx[j]], :], transposed via smem ----------
#define JT 64
__global__ __launch_bounds__(256)
void k2_gather(const int* __restrict__ in_idx, const int* __restrict__ out_idx,
               float* __restrict__ out, int n_out) {
    __shared__ float ys[JT][D + 1];
    __shared__ int cols[JT];

    int t = threadIdx.x;
    int j0 = blockIdx.x * JT;

    if (t < JT) {
        int jj = j0 + t;
        int c = 0;
        if (jj < n_out) {
            int oj = out_idx[jj];
            c = in_idx[oj];
        }
        cols[t] = c;
    }
    __syncthreads();

    int col = t >> 2;   // 0..63
    int sub = t & 3;    // 0..3
    long long c = cols[col];
    const float4* src = (const float4*)&g_yT[(size_t)c * D];
#pragma unroll
    for (int i = 0; i < 4; i++) {
        int q = i * 4 + sub;
        float4 v = src[q];
        float* dst = &ys[col][q * 4];
        dst[0] = v.x; dst[1] = v.y; dst[2] = v.z; dst[3] = v.w;
    }
    __syncthreads();

#pragma unroll
    for (int r = 0; r < 16; r++) {
        int flat = r * 256 + t;
        int d = flat >> 6;
        int jl = flat & 63;
        int jj = j0 + jl;
        if (jj < n_out)
            out[(size_t)d * n_out + jj] = ys[jl][d];
    }
}

extern "C" void kernel_launch(void* const* d_in, const int* in_sizes, int n_in,
                              void* d_out, int out_size) {
    const float* values  = (const float*)d_in[0];   // (64, M) row-major
    const float* weight  = (const float*)d_in[1];   // (64, 64) row-major
    const int*   in_idx  = (const int*)d_in[2];     // (N_IN,)
    const int*   out_idx = (const int*)d_in[3];     // (N_OUT,)
    float*       out     = (float*)d_out;           // (64, N_OUT) row-major

    int M     = in_sizes[0] / D;
    int n_out = in_sizes[3];

    int g1 = (M + 255) / 256;
    k1_gemm<<<g1, 128>>>(values, weight, M);

    int g2 = (n_out + JT - 1) / JT;
    k2_gather<<<g2, 256>>>(in_idx, out_idx, out, n_out);
}

// round 7
// speedup vs baseline: 1.9146x; 1.4284x over previous
#include <cuda_runtime.h>
#include <cuda_bf16.h>
#include <cstdint>

#define D 64
#define M_MAX 1000000

// Scratch: y_all^T, m-major: g_yT[m*64 + d] = (W @ values)[d, m]. (256 MB)
__device__ float g_yT[(size_t)M_MAX * D];

// ---------------- helpers ----------------
__device__ __forceinline__ uint32_t smem_u32(const void* p) {
    uint32_t a;
    asm("{ .reg .u64 t; cvta.to.shared.u64 t, %1; cvt.u32.u64 %0, t; }" : "=r"(a) : "l"(p));
    return a;
}
#define SW128(x) ((x) ^ (((x) >> 3) & 0x70))

__device__ __forceinline__ uint32_t pack_bf16x2(float lo_elem, float hi_elem) {
    __nv_bfloat162 h = __floats2bfloat162_rn(lo_elem, hi_elem);
    return *reinterpret_cast<uint32_t*>(&h);
}

// ldmatrix x4 (non-transposed), baseline PTX ISA — compiles on sm_103 base target.
__device__ __forceinline__ void ldsm4(uint32_t* r, uint32_t addr) {
    asm volatile("ldmatrix.sync.aligned.m8n8.x4.shared.b16 {%0,%1,%2,%3}, [%4];"
                 : "=r"(r[0]), "=r"(r[1]), "=r"(r[2]), "=r"(r[3]) : "r"(addr));
}

// mma.sync m16n8k16 row.col bf16 -> f32 accumulate (sm_80 baseline ISA).
__device__ __forceinline__ void mma16816(float* c, const uint32_t* a, const uint32_t* b) {
    asm volatile(
        "mma.sync.aligned.m16n8k16.row.col.f32.bf16.bf16.f32 "
        "{%0,%1,%2,%3}, {%4,%5,%6,%7}, {%8,%9}, {%0,%1,%2,%3};"
        : "+f"(c[0]), "+f"(c[1]), "+f"(c[2]), "+f"(c[3])
        : "r"(a[0]), "r"(a[1]), "r"(a[2]), "r"(a[3]), "r"(b[0]), "r"(b[1]));
}

// logical (row, k) -> swizzled byte offset within a tile stored as 128B rows
__device__ __forceinline__ uint32_t tile_off(int row, int k) {
    return SW128((uint32_t)((row >> 3) * 1024 + (row & 7) * 128 + k * 2));
}

// ---------- K1: y_all^T = (W @ values)^T via warp-level bf16 split-precision MMA ----------
// Block = 128 threads, one m-tile of 128 columns of values.
// A = values^T tile [128 x 64] bf16 (hi/lo), row-major m x k, SW128.
// B = W [64 x 64] bf16 (hi/lo), row-major d x k  (== col-major B for row.col mma).
// Each warp: 32 m-rows x 64 d.  3 products x 4 k16-steps x (2 m-tiles x 8 n-tiles).
__global__ __launch_bounds__(128)
void k1_tensor(const float* __restrict__ values, const float* __restrict__ weight, int M) {
    __shared__ char A_hi[16384];
    __shared__ char A_lo[16384];
    __shared__ char B_hi[8192];
    __shared__ char B_lo[8192];

    int t = threadIdx.x;
    int wid = t >> 5, lane = t & 31;

    // --- Stage W -> B_hi/B_lo (bf16 split), k-pair packed u32 ---
    #pragma unroll
    for (int i = 0; i < 16; i++) {
        int flat = i * 128 + t;          // 0..2047
        int d = flat >> 5;               // 0..63
        int kp = flat & 31;              // k-pair 0..31
        float2 w2 = *(const float2*)(weight + d * 64 + kp * 2);
        float h0 = __bfloat162float(__float2bfloat16_rn(w2.x));
        float h1 = __bfloat162float(__float2bfloat16_rn(w2.y));
        uint32_t off = tile_off(d, kp * 2);
        *(uint32_t*)(B_hi + off) = pack_bf16x2(h0, h1);
        *(uint32_t*)(B_lo + off) = pack_bf16x2(w2.x - h0, w2.y - h1);
    }

    // --- Stage + transpose values tile -> A_hi/A_lo ---
    long long m0 = (long long)blockIdx.x * 128;
    #pragma unroll
    for (int i = 0; i < 16; i++) {
        int flat = i * 128 + t;          // 32 kp x 64 mp
        int kp = flat >> 6;              // k-pair 0..31
        int mp = flat & 63;              // m-pair 0..63
        int k0 = kp * 2;
        long long mg = m0 + mp * 2;
        long long mc = (mg + 1 < (long long)M) ? mg : 0;   // clamp (tail rows never stored)
        float2 v0 = *(const float2*)(values + (size_t)k0 * M + mc);
        float2 v1 = *(const float2*)(values + (size_t)(k0 + 1) * M + mc);
        #pragma unroll
        for (int mm = 0; mm < 2; mm++) {
            float a = mm ? v0.y : v0.x;      // (k0,   m_local)
            float b = mm ? v1.y : v1.x;      // (k0+1, m_local)
            float ha = __bfloat162float(__float2bfloat16_rn(a));
            float hb = __bfloat162float(__float2bfloat16_rn(b));
            uint32_t off = tile_off(mp * 2 + mm, k0);
            *(uint32_t*)(A_hi + off) = pack_bf16x2(ha, hb);
            *(uint32_t*)(A_lo + off) = pack_bf16x2(a - ha, b - hb);
        }
    }
    __syncthreads();

    uint32_t a_hi_b = smem_u32(A_hi), a_lo_b = smem_u32(A_lo);
    uint32_t b_hi_b = smem_u32(B_hi), b_lo_b = smem_u32(B_lo);

    float acc[2][8][4];
    #pragma unroll
    for (int mt = 0; mt < 2; mt++)
        #pragma unroll
        for (int nt = 0; nt < 8; nt++)
            #pragma unroll
            for (int r = 0; r < 4; r++) acc[mt][nt][r] = 0.0f;

    int mbase = wid * 32;
    // ldmatrix lane->row/k mapping (see layout notes): A: ml = base + (lane&15), k += (lane>>4)*8
    int a_row_l = lane & 15;
    int a_k_l   = (lane >> 4) * 8;
    // B x4 covers 2 n-tiles: n = ntp*16 + (lane>>4)*8 + (lane&7), k += ((lane>>3)&1)*8
    int b_n_l = ((lane >> 4) << 3) + (lane & 7);
    int b_k_l = ((lane >> 3) & 1) * 8;

    #pragma unroll
    for (int p = 0; p < 3; p++) {
        uint32_t Ab = (p == 1) ? a_lo_b : a_hi_b;
        uint32_t Bb = (p == 2) ? b_lo_b : b_hi_b;
        #pragma unroll
        for (int ks = 0; ks < 4; ks++) {
            int k0 = ks * 16;
            uint32_t afr[2][4];
            #pragma unroll
            for (int mt = 0; mt < 2; mt++)
                ldsm4(afr[mt], Ab + tile_off(mbase + mt * 16 + a_row_l, k0 + a_k_l));
            #pragma unroll
            for (int ntp = 0; ntp < 4; ntp++) {
                uint32_t bfr[4];
                ldsm4(bfr, Bb + tile_off(ntp * 16 + b_n_l, k0 + b_k_l));
                #pragma unroll
                for (int mt = 0; mt < 2; mt++) {
                    mma16816(acc[mt][2 * ntp],     afr[mt], bfr);
                    mma16816(acc[mt][2 * ntp + 1], afr[mt], bfr + 2);
                }
            }
        }
    }

    // --- Epilogue: c0,c1 -> row g, cols tg*2,+1 ; c2,c3 -> row g+8 ---
    int g  = lane >> 2;
    int tg = lane & 3;
    #pragma unroll
    for (int mt = 0; mt < 2; mt++) {
        long long mA = m0 + mbase + mt * 16 + g;
        long long mB = mA + 8;
        #pragma unroll
        for (int nt = 0; nt < 8; nt++) {
            int d0 = nt * 8 + tg * 2;
            if (mA < (long long)M)
                *(float2*)&g_yT[(size_t)mA * D + d0] = make_float2(acc[mt][nt][0], acc[mt][nt][1]);
            if (mB < (long long)M)
                *(float2*)&g_yT[(size_t)mB * D + d0] = make_float2(acc[mt][nt][2], acc[mt][nt][3]);
        }
    }
}

// ---------- K2: out[:, j] = y_all^T[in_idx[out_idx[j]], :], transposed via smem ----------
#define JT 64
__global__ __launch_bounds__(256)
void k2_gather(const int* __restrict__ in_idx, const int* __restrict__ out_idx,
               float* __restrict__ out, int n_out) {
    __shared__ float ys[JT][D + 1];
    __shared__ int cols[JT];

    int t = threadIdx.x;
    int j0 = blockIdx.x * JT;

    if (t < JT) {
        int jj = j0 + t;
        int c = 0;
        if (jj < n_out) {
            int oj = out_idx[jj];
            c = in_idx[oj];
        }
        cols[t] = c;
    }
    __syncthreads();

    int col = t >> 2;
    int sub = t & 3;
    long long c = cols[col];
    const float4* src = (const float4*)&g_yT[(size_t)c * D];
#pragma unroll
    for (int i = 0; i < 4; i++) {
        int q = i * 4 + sub;
        float4 v = src[q];
        float* dst = &ys[col][q * 4];
        dst[0] = v.x; dst[1] = v.y; dst[2] = v.z; dst[3] = v.w;
    }
    __syncthreads();

#pragma unroll
    for (int r = 0; r < 16; r++) {
        int flat = r * 256 + t;
        int d = flat >> 6;
        int jl = flat & 63;
        int jj = j0 + jl;
        if (jj < n_out)
            out[(size_t)d * n_out + jj] = ys[jl][d];
    }
}

extern "C" void kernel_launch(void* const* d_in, const int* in_sizes, int n_in,
                              void* d_out, int out_size) {
    const float* values  = (const float*)d_in[0];   // (64, M) row-major
    const float* weight  = (const float*)d_in[1];   // (64, 64) row-major
    const int*   in_idx  = (const int*)d_in[2];     // (N_IN,)
    const int*   out_idx = (const int*)d_in[3];     // (N_OUT,)
    float*       out     = (float*)d_out;           // (64, N_OUT) row-major

    int M     = in_sizes[0] / D;
    int n_out = in_sizes[3];

    int g1 = (M + 127) / 128;
    k1_tensor<<<g1, 128>>>(values, weight, M);

    int g2 = (n_out + JT - 1) / JT;
    k2_gather<<<g2, 256>>>(in_idx, out_idx, out, n_out);
}

// round 8
// speedup vs baseline: 2.0929x; 1.0931x over previous
#include <cuda_runtime.h>
#include <cuda_bf16.h>
#include <cuda_fp16.h>
#include <cstdint>

#define D 64
#define M_MAX 1000000

// Scratch: y_all^T in fp16, m-major: g_yT[m*64 + d] = (W @ values)[d, m]. (128 MB)
// fp16 storage: ~2e-4 aggregate rel err, 5x under the 1e-3 threshold; halves
// both K1 write traffic and K2 gather-read traffic.
__device__ __half g_yT[(size_t)M_MAX * D];

// ---------------- helpers ----------------
__device__ __forceinline__ uint32_t smem_u32(const void* p) {
    uint32_t a;
    asm("{ .reg .u64 t; cvta.to.shared.u64 t, %1; cvt.u32.u64 %0, t; }" : "=r"(a) : "l"(p));
    return a;
}
#define SW128(x) ((x) ^ (((x) >> 3) & 0x70))

__device__ __forceinline__ uint32_t pack_bf16x2(float lo_elem, float hi_elem) {
    __nv_bfloat162 h = __floats2bfloat162_rn(lo_elem, hi_elem);
    return *reinterpret_cast<uint32_t*>(&h);
}

// ldmatrix x4 (non-transposed), baseline PTX ISA.
__device__ __forceinline__ void ldsm4(uint32_t* r, uint32_t addr) {
    asm volatile("ldmatrix.sync.aligned.m8n8.x4.shared.b16 {%0,%1,%2,%3}, [%4];"
                 : "=r"(r[0]), "=r"(r[1]), "=r"(r[2]), "=r"(r[3]) : "r"(addr));
}

// mma.sync m16n8k16 row.col bf16 -> f32 accumulate.
__device__ __forceinline__ void mma16816(float* c, const uint32_t* a, const uint32_t* b) {
    asm volatile(
        "mma.sync.aligned.m16n8k16.row.col.f32.bf16.bf16.f32 "
        "{%0,%1,%2,%3}, {%4,%5,%6,%7}, {%8,%9}, {%0,%1,%2,%3};"
        : "+f"(c[0]), "+f"(c[1]), "+f"(c[2]), "+f"(c[3])
        : "r"(a[0]), "r"(a[1]), "r"(a[2]), "r"(a[3]), "r"(b[0]), "r"(b[1]));
}

// logical (row, k) -> swizzled byte offset within a tile stored as 128B rows
__device__ __forceinline__ uint32_t tile_off(int row, int k) {
    return SW128((uint32_t)((row >> 3) * 1024 + (row & 7) * 128 + k * 2));
}

// ---------- K1: y_all^T = (W @ values)^T via warp-level bf16 split-precision MMA ----------
__global__ __launch_bounds__(128)
void k1_tensor(const float* __restrict__ values, const float* __restrict__ weight, int M) {
    __shared__ char A_hi[16384];
    __shared__ char A_lo[16384];
    __shared__ char B_hi[8192];
    __shared__ char B_lo[8192];

    int t = threadIdx.x;
    int wid = t >> 5, lane = t & 31;

    // --- Stage W -> B_hi/B_lo (bf16 split) ---
    #pragma unroll
    for (int i = 0; i < 16; i++) {
        int flat = i * 128 + t;
        int d = flat >> 5;               // 0..63
        int kp = flat & 31;              // k-pair 0..31
        float2 w2 = *(const float2*)(weight + d * 64 + kp * 2);
        float h0 = __bfloat162float(__float2bfloat16_rn(w2.x));
        float h1 = __bfloat162float(__float2bfloat16_rn(w2.y));
        uint32_t off = tile_off(d, kp * 2);
        *(uint32_t*)(B_hi + off) = pack_bf16x2(h0, h1);
        *(uint32_t*)(B_lo + off) = pack_bf16x2(w2.x - h0, w2.y - h1);
    }

    // --- Stage + transpose values tile -> A_hi/A_lo ---
    long long m0 = (long long)blockIdx.x * 128;
    #pragma unroll
    for (int i = 0; i < 16; i++) {
        int flat = i * 128 + t;          // 32 kp x 64 mp
        int kp = flat >> 6;
        int mp = flat & 63;
        int k0 = kp * 2;
        long long mg = m0 + mp * 2;
        long long mc = (mg + 1 < (long long)M) ? mg : 0;
        float2 v0 = *(const float2*)(values + (size_t)k0 * M + mc);
        float2 v1 = *(const float2*)(values + (size_t)(k0 + 1) * M + mc);
        #pragma unroll
        for (int mm = 0; mm < 2; mm++) {
            float a = mm ? v0.y : v0.x;
            float b = mm ? v1.y : v1.x;
            float ha = __bfloat162float(__float2bfloat16_rn(a));
            float hb = __bfloat162float(__float2bfloat16_rn(b));
            uint32_t off = tile_off(mp * 2 + mm, k0);
            *(uint32_t*)(A_hi + off) = pack_bf16x2(ha, hb);
            *(uint32_t*)(A_lo + off) = pack_bf16x2(a - ha, b - hb);
        }
    }
    __syncthreads();

    uint32_t a_hi_b = smem_u32(A_hi), a_lo_b = smem_u32(A_lo);
    uint32_t b_hi_b = smem_u32(B_hi), b_lo_b = smem_u32(B_lo);

    float acc[2][8][4];
    #pragma unroll
    for (int mt = 0; mt < 2; mt++)
        #pragma unroll
        for (int nt = 0; nt < 8; nt++)
            #pragma unroll
            for (int r = 0; r < 4; r++) acc[mt][nt][r] = 0.0f;

    int mbase = wid * 32;
    int a_row_l = lane & 15;
    int a_k_l   = (lane >> 4) * 8;
    int b_n_l = ((lane >> 4) << 3) + (lane & 7);
    int b_k_l = ((lane >> 3) & 1) * 8;

    #pragma unroll
    for (int p = 0; p < 3; p++) {
        uint32_t Ab = (p == 1) ? a_lo_b : a_hi_b;
        uint32_t Bb = (p == 2) ? b_lo_b : b_hi_b;
        #pragma unroll
        for (int ks = 0; ks < 4; ks++) {
            int k0 = ks * 16;
            uint32_t afr[2][4];
            #pragma unroll
            for (int mt = 0; mt < 2; mt++)
                ldsm4(afr[mt], Ab + tile_off(mbase + mt * 16 + a_row_l, k0 + a_k_l));
            #pragma unroll
            for (int ntp = 0; ntp < 4; ntp++) {
                uint32_t bfr[4];
                ldsm4(bfr, Bb + tile_off(ntp * 16 + b_n_l, k0 + b_k_l));
                #pragma unroll
                for (int mt = 0; mt < 2; mt++) {
                    mma16816(acc[mt][2 * ntp],     afr[mt], bfr);
                    mma16816(acc[mt][2 * ntp + 1], afr[mt], bfr + 2);
                }
            }
        }
    }

    // --- Epilogue: fp32 acc -> fp16, m-major rows (64 halfs = 128B per m) ---
    int g  = lane >> 2;
    int tg = lane & 3;
    #pragma unroll
    for (int mt = 0; mt < 2; mt++) {
        long long mA = m0 + mbase + mt * 16 + g;
        long long mB = mA + 8;
        #pragma unroll
        for (int nt = 0; nt < 8; nt++) {
            int d0 = nt * 8 + tg * 2;
            if (mA < (long long)M)
                *(__half2*)&g_yT[(size_t)mA * D + d0] =
                    __floats2half2_rn(acc[mt][nt][0], acc[mt][nt][1]);
            if (mB < (long long)M)
                *(__half2*)&g_yT[(size_t)mB * D + d0] =
                    __floats2half2_rn(acc[mt][nt][2], acc[mt][nt][3]);
        }
    }
}

// ---------- K2: out[:, j] = fp32(y_all^T[in_idx[out_idx[j]], :]), transposed via smem ----------
#define JT 64
__global__ __launch_bounds__(256)
void k2_gather(const int* __restrict__ in_idx, const int* __restrict__ out_idx,
               float* __restrict__ out, int n_out) {
    __shared__ float ys[JT][D + 1];
    __shared__ int cols[JT];

    int t = threadIdx.x;
    int j0 = blockIdx.x * JT;

    if (t < JT) {
        int jj = j0 + t;
        int c = 0;
        if (jj < n_out) {
            int oj = out_idx[jj];
            c = in_idx[oj];
        }
        cols[t] = c;
    }
    __syncthreads();

    // Gather: 4 threads/col, each loads 2x uint4 (16B = 8 halfs); 128B per column.
    int col = t >> 2;   // 0..63
    int sub = t & 3;    // 0..3
    long long c = cols[col];
    const uint4* src = (const uint4*)&g_yT[(size_t)c * D];   // 8 x uint4 per column
#pragma unroll
    for (int i = 0; i < 2; i++) {
        int q = i * 4 + sub;             // uint4 index 0..7
        uint4 v = src[q];
        float* dst = &ys[col][q * 8];
        float2 f;
        f = __half22float2(*(__half2*)&v.x); dst[0] = f.x; dst[1] = f.y;
        f = __half22float2(*(__half2*)&v.y); dst[2] = f.x; dst[3] = f.y;
        f = __half22float2(*(__half2*)&v.z); dst[4] = f.x; dst[5] = f.y;
        f = __half22float2(*(__half2*)&v.w); dst[6] = f.x; dst[7] = f.y;
    }
    __syncthreads();

    // Transposed write-out: 128B-coalesced along j per d-row.
#pragma unroll
    for (int r = 0; r < 16; r++) {
        int flat = r * 256 + t;
        int d = flat >> 6;
        int jl = flat & 63;
        int jj = j0 + jl;
        if (jj < n_out)
            out[(size_t)d * n_out + jj] = ys[jl][d];
    }
}

extern "C" void kernel_launch(void* const* d_in, const int* in_sizes, int n_in,
                              void* d_out, int out_size) {
    const float* values  = (const float*)d_in[0];   // (64, M) row-major
    const float* weight  = (const float*)d_in[1];   // (64, 64) row-major
    const int*   in_idx  = (const int*)d_in[2];     // (N_IN,)
    const int*   out_idx = (const int*)d_in[3];     // (N_OUT,)
    float*       out     = (float*)d_out;           // (64, N_OUT) row-major

    int M     = in_sizes[0] / D;
    int n_out = in_sizes[3];

    int g1 = (M + 127) / 128;
    k1_tensor<<<g1, 128>>>(values, weight, M);

    int g2 = (n_out + JT - 1) / JT;
    k2_gather<<<g2, 256>>>(in_idx, out_idx, out, n_out);
}

// round 9
// speedup vs baseline: 2.1591x; 1.0316x over previous
#include <cuda_runtime.h>
#include <cuda_fp16.h>
#include <cstdint>

#define D 64
#define M_MAX 1000000

// Scratch: y_all^T in fp16, m-major: g_yT[m*64 + d] = (W @ values)[d, m]. (128 MB)
__device__ __half g_yT[(size_t)M_MAX * D];

// ---------------- helpers ----------------
__device__ __forceinline__ uint32_t smem_u32(const void* p) {
    uint32_t a;
    asm("{ .reg .u64 t; cvta.to.shared.u64 t, %1; cvt.u32.u64 %0, t; }" : "=r"(a) : "l"(p));
    return a;
}
#define SW128(x) ((x) ^ (((x) >> 3) & 0x70))

__device__ __forceinline__ uint32_t pack_f16x2(float lo_elem, float hi_elem) {
    __half2 h = __floats2half2_rn(lo_elem, hi_elem);   // .x = low 16 bits
    return *reinterpret_cast<uint32_t*>(&h);
}

// ldmatrix x4 (non-transposed), baseline PTX ISA.
__device__ __forceinline__ void ldsm4(uint32_t* r, uint32_t addr) {
    asm volatile("ldmatrix.sync.aligned.m8n8.x4.shared.b16 {%0,%1,%2,%3}, [%4];"
                 : "=r"(r[0]), "=r"(r[1]), "=r"(r[2]), "=r"(r[3]) : "r"(addr));
}

// mma.sync m16n8k16 row.col fp16 -> f32 accumulate.
__device__ __forceinline__ void mma16816(float* c, const uint32_t* a, const uint32_t* b) {
    asm volatile(
        "mma.sync.aligned.m16n8k16.row.col.f32.f16.f16.f32 "
        "{%0,%1,%2,%3}, {%4,%5,%6,%7}, {%8,%9}, {%0,%1,%2,%3};"
        : "+f"(c[0]), "+f"(c[1]), "+f"(c[2]), "+f"(c[3])
        : "r"(a[0]), "r"(a[1]), "r"(a[2]), "r"(a[3]), "r"(b[0]), "r"(b[1]));
}

// logical (row, k) -> swizzled byte offset within a tile stored as 128B rows
__device__ __forceinline__ uint32_t tile_off(int row, int k) {
    return SW128((uint32_t)((row >> 3) * 1024 + (row & 7) * 128 + k * 2));
}

// ---------- K1: y_all^T = (W @ values)^T, 2-product fp16 split MMA ----------
// A = values^T tile [128 x 64], split hi+lo fp16 (error 2^-22).
// B = W [64 x 64] single fp16 (one rounding, rel ~2^-11 -> y rel ~2.8e-4).
// y = A_hi*B + A_lo*B : 2 products sharing B fragments (B ldsm hoisted).
__global__ __launch_bounds__(128)
void k1_tensor(const float* __restrict__ values, const float* __restrict__ weight, int M) {
    __shared__ char A_hi[16384];
    __shared__ char A_lo[16384];
    __shared__ char B_h[8192];

    int t = threadIdx.x;
    int wid = t >> 5, lane = t & 31;

    // --- Stage W -> B_h (single fp16) ---
    #pragma unroll
    for (int i = 0; i < 16; i++) {
        int flat = i * 128 + t;
        int d = flat >> 5;               // 0..63
        int kp = flat & 31;              // k-pair 0..31
        float2 w2 = *(const float2*)(weight + d * 64 + kp * 2);
        *(uint32_t*)(B_h + tile_off(d, kp * 2)) = pack_f16x2(w2.x, w2.y);
    }

    // --- Stage + transpose values tile -> A_hi/A_lo (fp16 split) ---
    long long m0 = (long long)blockIdx.x * 128;
    #pragma unroll
    for (int i = 0; i < 16; i++) {
        int flat = i * 128 + t;          // 32 kp x 64 mp
        int kp = flat >> 6;
        int mp = flat & 63;
        int k0 = kp * 2;
        long long mg = m0 + mp * 2;
        long long mc = (mg + 1 < (long long)M) ? mg : 0;
        float2 v0 = *(const float2*)(values + (size_t)k0 * M + mc);
        float2 v1 = *(const float2*)(values + (size_t)(k0 + 1) * M + mc);
        #pragma unroll
        for (int mm = 0; mm < 2; mm++) {
            float a = mm ? v0.y : v0.x;      // (k0,   m_local)
            float b = mm ? v1.y : v1.x;      // (k0+1, m_local)
            float ha = __half2float(__float2half_rn(a));
            float hb = __half2float(__float2half_rn(b));
            uint32_t off = tile_off(mp * 2 + mm, k0);
            *(uint32_t*)(A_hi + off) = pack_f16x2(ha, hb);
            *(uint32_t*)(A_lo + off) = pack_f16x2(a - ha, b - hb);
        }
    }
    __syncthreads();

    uint32_t a_hi_b = smem_u32(A_hi), a_lo_b = smem_u32(A_lo);
    uint32_t b_h_b  = smem_u32(B_h);

    float acc[2][8][4];
    #pragma unroll
    for (int mt = 0; mt < 2; mt++)
        #pragma unroll
        for (int nt = 0; nt < 8; nt++)
            #pragma unroll
            for (int r = 0; r < 4; r++) acc[mt][nt][r] = 0.0f;

    int mbase = wid * 32;
    int a_row_l = lane & 15;
    int a_k_l   = (lane >> 4) * 8;
    int b_n_l = ((lane >> 4) << 3) + (lane & 7);
    int b_k_l = ((lane >> 3) & 1) * 8;

    #pragma unroll
    for (int ks = 0; ks < 4; ks++) {
        int k0 = ks * 16;
        // B fragments once per k-step, shared by both A products
        uint32_t bfr[4][4];
        #pragma unroll
        for (int ntp = 0; ntp < 4; ntp++)
            ldsm4(bfr[ntp], b_h_b + tile_off(ntp * 16 + b_n_l, k0 + b_k_l));
        #pragma unroll
        for (int p = 0; p < 2; p++) {
            uint32_t Ab = p ? a_lo_b : a_hi_b;
            uint32_t afr[2][4];
            #pragma unroll
            for (int mt = 0; mt < 2; mt++)
                ldsm4(afr[mt], Ab + tile_off(mbase + mt * 16 + a_row_l, k0 + a_k_l));
            #pragma unroll
            for (int ntp = 0; ntp < 4; ntp++)
                #pragma unroll
                for (int mt = 0; mt < 2; mt++) {
                    mma16816(acc[mt][2 * ntp],     afr[mt], bfr[ntp]);
                    mma16816(acc[mt][2 * ntp + 1], afr[mt], bfr[ntp] + 2);
                }
        }
    }

    // --- Epilogue: fp32 acc -> fp16, m-major rows (64 halfs = 128B per m) ---
    int g  = lane >> 2;
    int tg = lane & 3;
    #pragma unroll
    for (int mt = 0; mt < 2; mt++) {
        long long mA = m0 + mbase + mt * 16 + g;
        long long mB = mA + 8;
        #pragma unroll
        for (int nt = 0; nt < 8; nt++) {
            int d0 = nt * 8 + tg * 2;
            if (mA < (long long)M)
                *(__half2*)&g_yT[(size_t)mA * D + d0] =
                    __floats2half2_rn(acc[mt][nt][0], acc[mt][nt][1]);
            if (mB < (long long)M)
                *(__half2*)&g_yT[(size_t)mB * D + d0] =
                    __floats2half2_rn(acc[mt][nt][2], acc[mt][nt][3]);
        }
    }
}

// ---------- K2: out[:, j] = fp32(y_all^T[in_idx[out_idx[j]], :]), transposed via smem ----------
#define JT 64
__global__ __launch_bounds__(256)
void k2_gather(const int* __restrict__ in_idx, const int* __restrict__ out_idx,
               float* __restrict__ out, int n_out) {
    __shared__ float ys[JT][D + 1];
    __shared__ int cols[JT];

    int t = threadIdx.x;
    int j0 = blockIdx.x * JT;

    if (t < JT) {
        int jj = j0 + t;
        int c = 0;
        if (jj < n_out) {
            int oj = out_idx[jj];
            c = in_idx[oj];
        }
        cols[t] = c;
    }
    __syncthreads();

    int col = t >> 2;   // 0..63
    int sub = t & 3;    // 0..3
    long long c = cols[col];
    const uint4* src = (const uint4*)&g_yT[(size_t)c * D];
#pragma unroll
    for (int i = 0; i < 2; i++) {
        int q = i * 4 + sub;             // uint4 index 0..7
        uint4 v = src[q];
        float* dst = &ys[col][q * 8];
        float2 f;
        f = __half22float2(*(__half2*)&v.x); dst[0] = f.x; dst[1] = f.y;
        f = __half22float2(*(__half2*)&v.y); dst[2] = f.x; dst[3] = f.y;
        f = __half22float2(*(__half2*)&v.z); dst[4] = f.x; dst[5] = f.y;
        f = __half22float2(*(__half2*)&v.w); dst[6] = f.x; dst[7] = f.y;
    }
    __syncthreads();

#pragma unroll
    for (int r = 0; r < 16; r++) {
        int flat = r * 256 + t;
        int d = flat >> 6;
        int jl = flat & 63;
        int jj = j0 + jl;
        if (jj < n_out)
            out[(size_t)d * n_out + jj] = ys[jl][d];
    }
}

extern "C" void kernel_launch(void* const* d_in, const int* in_sizes, int n_in,
                              void* d_out, int out_size) {
    const float* values  = (const float*)d_in[0];   // (64, M) row-major
    const float* weight  = (const float*)d_in[1];   // (64, 64) row-major
    const int*   in_idx  = (const int*)d_in[2];     // (N_IN,)
    const int*   out_idx = (const int*)d_in[3];     // (N_OUT,)
    float*       out     = (float*)d_out;           // (64, N_OUT) row-major

    int M     = in_sizes[0] / D;
    int n_out = in_sizes[3];

    int g1 = (M + 127) / 128;
    k1_tensor<<<g1, 128>>>(values, weight, M);

    int g2 = (n_out + JT - 1) / JT;
    k2_gather<<<g2, 256>>>(in_idx, out_idx, out, n_out);
}

// round 11
// speedup vs baseline: 2.3495x; 1.0882x over previous
#include <cuda_runtime.h>
#include <cuda_fp16.h>
#include <cstdint>

#define D 64
#define M_MAX 1000000

// Scratch: y_all^T in fp16, m-major: g_yT[m*64 + d] = (W @ values)[d, m]. (128 MB)
__device__ __half g_yT[(size_t)M_MAX * D];

// ---------------- helpers ----------------
__device__ __forceinline__ uint32_t smem_u32(const void* p) {
    uint32_t a;
    asm("{ .reg .u64 t; cvta.to.shared.u64 t, %1; cvt.u32.u64 %0, t; }" : "=r"(a) : "l"(p));
    return a;
}

__device__ __forceinline__ uint32_t pack_f16x2(float lo_elem, float hi_elem) {
    __half2 h = __floats2half2_rn(lo_elem, hi_elem);   // .x = low 16 bits
    return *reinterpret_cast<uint32_t*>(&h);
}

// ldmatrix x4 (non-transposed), baseline PTX ISA.
__device__ __forceinline__ void ldsm4(uint32_t* r, uint32_t addr) {
    asm volatile("ldmatrix.sync.aligned.m8n8.x4.shared.b16 {%0,%1,%2,%3}, [%4];"
                 : "=r"(r[0]), "=r"(r[1]), "=r"(r[2]), "=r"(r[3]) : "r"(addr));
}

// mma.sync m16n8k16 row.col fp16 -> f32 accumulate.
__device__ __forceinline__ void mma16816(float* c, const uint32_t* a, const uint32_t* b) {
    asm volatile(
        "mma.sync.aligned.m16n8k16.row.col.f32.f16.f16.f32 "
        "{%0,%1,%2,%3}, {%4,%5,%6,%7}, {%8,%9}, {%0,%1,%2,%3};"
        : "+f"(c[0]), "+f"(c[1]), "+f"(c[2]), "+f"(c[3])
        : "r"(a[0]), "r"(a[1]), "r"(a[2]), "r"(a[3]), "r"(b[0]), "r"(b[1]));
}

// Padded layout: row stride 144B (128B data + 16B pad).
// bank(row) = row*36 mod 32 = 4*row mod 32 -> every 8-lane phase of an STS.128
// with consecutive rows covers all 32 banks: conflict-free transpose stores.
// ldmatrix takes arbitrary 16B-aligned per-lane addresses, so reads are fine.
#define ROWSTRIDE 144
__device__ __forceinline__ uint32_t off144(int row, int k) {   // k in halfs (multiple of 8)
    return (uint32_t)(row * ROWSTRIDE + (k >> 3) * 16);
}

__device__ __forceinline__ void sts128(uint32_t addr, uint32_t r0, uint32_t r1, uint32_t r2, uint32_t r3) {
    asm volatile("st.shared.v4.b32 [%0], {%1,%2,%3,%4};"
                 :: "r"(addr), "r"(r0), "r"(r1), "r"(r2), "r"(r3) : "memory");
}

// ---------- K1: y_all^T = (W @ values)^T, 2-product fp16 split MMA ----------
// A = values^T tile [128 x 64], split hi+lo fp16 (error 2^-22).
// B = W [64 x 64] single fp16.
// Conflict-free padded smem; thread t owns column m0+t (64 coalesced LDG.32).
__global__ __launch_bounds__(128)
void k1_tensor(const float* __restrict__ values, const float* __restrict__ weight, int M) {
    __shared__ __align__(16) char A_hi[128 * ROWSTRIDE];   // 18432 B
    __shared__ __align__(16) char A_lo[128 * ROWSTRIDE];   // 18432 B
    __shared__ __align__(16) char B_h[64 * ROWSTRIDE];     //  9216 B

    int t = threadIdx.x;
    int wid = t >> 5, lane = t & 31;
    uint32_t a_hi_b = smem_u32(A_hi), a_lo_b = smem_u32(A_lo), b_h_b = smem_u32(B_h);

    // --- Stage W -> B_h: thread t handles row d = t>>1, k-halfs [(t&1)*32, +32) ---
    // Each q: 8 halfs = 2 float4 loads = 1 STS.128. 4 q-steps cover 32 halfs.
    {
        int d = t >> 1;
        int kh = (t & 1) * 32;
        const float* wrow = weight + d * 64 + kh;
        #pragma unroll
        for (int q = 0; q < 4; q++) {
            float4 wa = *(const float4*)(wrow + q * 8);
            float4 wb = *(const float4*)(wrow + q * 8 + 4);
            uint32_t p0 = pack_f16x2(wa.x, wa.y);
            uint32_t p1 = pack_f16x2(wa.z, wa.w);
            uint32_t p2 = pack_f16x2(wb.x, wb.y);
            uint32_t p3 = pack_f16x2(wb.z, wb.w);
            sts128(b_h_b + off144(d, kh + q * 8), p0, p1, p2, p3);
        }
    }

    // --- Stage + transpose values -> A_hi/A_lo: thread t owns column m = m0+t ---
    long long m0 = (long long)blockIdx.x * 128;
    {
        long long mg = m0 + t;
        const float* src = values + ((mg < (long long)M) ? mg : 0);
        float v[64];
        #pragma unroll
        for (int k = 0; k < 64; k++)
            v[k] = __ldg(src + (size_t)k * M);       // coalesced 128B/warp, MLP ~64
        #pragma unroll
        for (int kg = 0; kg < 8; kg++) {
            uint32_t hi[4], lo[4];
            #pragma unroll
            for (int j = 0; j < 4; j++) {
                float a = v[kg * 8 + 2 * j];
                float b = v[kg * 8 + 2 * j + 1];
                float ha = __half2float(__float2half_rn(a));
                float hb = __half2float(__float2half_rn(b));
                hi[j] = pack_f16x2(ha, hb);
                lo[j] = pack_f16x2(a - ha, b - hb);
            }
            sts128(a_hi_b + off144(t, kg * 8), hi[0], hi[1], hi[2], hi[3]);
            sts128(a_lo_b + off144(t, kg * 8), lo[0], lo[1], lo[2], lo[3]);
        }
    }
    __syncthreads();

    float acc[2][8][4];
    #pragma unroll
    for (int mt = 0; mt < 2; mt++)
        #pragma unroll
        for (int nt = 0; nt < 8; nt++)
            #pragma unroll
            for (int r = 0; r < 4; r++) acc[mt][nt][r] = 0.0f;

    int mbase = wid * 32;
    int a_row_l = lane & 15;
    int a_k_l   = (lane >> 4) * 8;
    int b_n_l = ((lane >> 4) << 3) + (lane & 7);
    int b_k_l = ((lane >> 3) & 1) * 8;

    #pragma unroll
    for (int ks = 0; ks < 4; ks++) {
        int k0 = ks * 16;
        uint32_t bfr[4][4];
        #pragma unroll
        for (int ntp = 0; ntp < 4; ntp++)
            ldsm4(bfr[ntp], b_h_b + off144(ntp * 16 + b_n_l, k0 + b_k_l));
        #pragma unroll
        for (int p = 0; p < 2; p++) {
            uint32_t Ab = p ? a_lo_b : a_hi_b;
            uint32_t afr[2][4];
            #pragma unroll
            for (int mt = 0; mt < 2; mt++)
                ldsm4(afr[mt], Ab + off144(mbase + mt * 16 + a_row_l, k0 + a_k_l));
            #pragma unroll
            for (int ntp = 0; ntp < 4; ntp++)
                #pragma unroll
                for (int mt = 0; mt < 2; mt++) {
                    mma16816(acc[mt][2 * ntp],     afr[mt], bfr[ntp]);
                    mma16816(acc[mt][2 * ntp + 1], afr[mt], bfr[ntp] + 2);
                }
        }
    }

    // --- Epilogue: fp32 acc -> fp16, m-major rows (64 halfs = 128B per m) ---
    int g  = lane >> 2;
    int tg = lane & 3;
    #pragma unroll
    for (int mt = 0; mt < 2; mt++) {
        long long mA = m0 + mbase + mt * 16 + g;
        long long mB = mA + 8;
        #pragma unroll
        for (int nt = 0; nt < 8; nt++) {
            int d0 = nt * 8 + tg * 2;
            if (mA < (long long)M)
                *(__half2*)&g_yT[(size_t)mA * D + d0] =
                    __floats2half2_rn(acc[mt][nt][0], acc[mt][nt][1]);
            if (mB < (long long)M)
                *(__half2*)&g_yT[(size_t)mB * D + d0] =
                    __floats2half2_rn(acc[mt][nt][2], acc[mt][nt][3]);
        }
    }
}

// ---------- K2: out[:, j] = fp32(y_all^T[in_idx[out_idx[j]], :]), transposed via smem ----------
#define JT 64
__global__ __launch_bounds__(256)
void k2_gather(const int* __restrict__ in_idx, const int* __restrict__ out_idx,
               float* __restrict__ out, int n_out) {
    __shared__ float ys[JT][D + 1];
    __shared__ int cols[JT];

    int t = threadIdx.x;
    int j0 = blockIdx.x * JT;

    if (t < JT) {
        int jj = j0 + t;
        int c = 0;
        if (jj < n_out) {
            int oj = out_idx[jj];
            c = in_idx[oj];
        }
        cols[t] = c;
    }
    __syncthreads();

    int col = t >> 2;   // 0..63
    int sub = t & 3;    // 0..3
    long long c = cols[col];
    const uint4* src = (const uint4*)&g_yT[(size_t)c * D];
#pragma unroll
    for (int i = 0; i < 2; i++) {
        int q = i * 4 + sub;             // uint4 index 0..7
        uint4 v = src[q];
        float* dst = &ys[col][q * 8];
        float2 f;
        f = __half22float2(*(__half2*)&v.x); dst[0] = f.x; dst[1] = f.y;
        f = __half22float2(*(__half2*)&v.y); dst[2] = f.x; dst[3] = f.y;
        f = __half22float2(*(__half2*)&v.z); dst[4] = f.x; dst[5] = f.y;
        f = __half22float2(*(__half2*)&v.w); dst[6] = f.x; dst[7] = f.y;
    }
    __syncthreads();

#pragma unroll
    for (int r = 0; r < 16; r++) {
        int flat = r * 256 + t;
        int d = flat >> 6;
        int jl = flat & 63;
        int jj = j0 + jl;
        if (jj < n_out)
            out[(size_t)d * n_out + jj] = ys[jl][d];
    }
}

extern "C" void kernel_launch(void* const* d_in, const int* in_sizes, int n_in,
                              void* d_out, int out_size) {
    const float* values  = (const float*)d_in[0];   // (64, M) row-major
    const float* weight  = (const float*)d_in[1];   // (64, 64) row-major
    const int*   in_idx  = (const int*)d_in[2];     // (N_IN,)
    const int*   out_idx = (const int*)d_in[3];     // (N_OUT,)
    float*       out     = (float*)d_out;           // (64, N_OUT) row-major

    int M     = in_sizes[0] / D;
    int n_out = in_sizes[3];

    int g1 = (M + 127) / 128;
    k1_tensor<<<g1, 128>>>(values, weight, M);

    int g2 = (n_out + JT - 1) / JT;
    k2_gather<<<g2, 256>>>(in_idx, out_idx, out, n_out);
}